// round 11
// baseline (speedup 1.0000x reference)
#include <cuda_runtime.h>
#include <cuda_fp16.h>
#include <cstdint>

#define BATCH   65536
#define DIM     128
#define NPROTO  512
#define ODIM    8
#define MTILE   128
#define NCHUNK  32
#define NCHUNKS 16
#define NTHREADS 512

#define ASTRIDE 272
#define ATILE   (MTILE * ASTRIDE)      // 34816 per split
#define MATB    (NCHUNK * ASTRIDE)     // 8704 per B split
#define BBUF    (2 * MATB)             // 17408 per buffer

#define SM_BIAS 0
#define SM_A    2048
#define SM_B    (SM_A + 2 * ATILE)     // 71680
#define SM_RED  SM_A
#define SMEM_TOTAL (SM_B + 2 * BBUF)   // 106496

__device__ __align__(16) __half g_w[2][NPROTO * DIM];  // h/m fp16 split of r^2*proto
__device__ float g_bias[NPROTO];

// ---------------- helpers ----------------
__device__ __forceinline__ uint32_t smem_u32(const void* p) {
    uint32_t a;
    asm("{ .reg .u64 t; cvta.to.shared.u64 t, %1; cvt.u32.u64 %0, t; }" : "=r"(a) : "l"(p));
    return a;
}
__device__ __forceinline__ void ldsm4(uint32_t* r, uint32_t a) {
    asm volatile("ldmatrix.sync.aligned.m8n8.x4.shared.b16 {%0,%1,%2,%3}, [%4];"
                 : "=r"(r[0]), "=r"(r[1]), "=r"(r[2]), "=r"(r[3]) : "r"(a));
}
__device__ __forceinline__ void ldsm2(uint32_t* r, uint32_t a) {
    asm volatile("ldmatrix.sync.aligned.m8n8.x2.shared.b16 {%0,%1}, [%2];"
                 : "=r"(r[0]), "=r"(r[1]) : "r"(a));
}
// fp32-accumulate MMA (main hh term)
__device__ __forceinline__ void mma_f32(float* d, const uint32_t* a, const uint32_t* b) {
    asm volatile(
        "mma.sync.aligned.m16n8k16.row.col.f32.f16.f16.f32 "
        "{%0,%1,%2,%3}, {%4,%5,%6,%7}, {%8,%9}, {%0,%1,%2,%3};"
        : "+f"(d[0]), "+f"(d[1]), "+f"(d[2]), "+f"(d[3])
        : "r"(a[0]), "r"(a[1]), "r"(a[2]), "r"(a[3]), "r"(b[0]), "r"(b[1]));
}
// fp16-accumulate MMA (tiny correction terms)
__device__ __forceinline__ void mma_f16(uint32_t* d, const uint32_t* a, const uint32_t* b) {
    asm volatile(
        "mma.sync.aligned.m16n8k16.row.col.f16.f16.f16.f16 "
        "{%0,%1}, {%2,%3,%4,%5}, {%6,%7}, {%0,%1};"
        : "+r"(d[0]), "+r"(d[1])
        : "r"(a[0]), "r"(a[1]), "r"(a[2]), "r"(a[3]), "r"(b[0]), "r"(b[1]));
}
__device__ __forceinline__ void cp_async16(uint32_t dst, const void* src) {
    asm volatile("cp.async.cg.shared.global [%0], [%1], 16;" :: "r"(dst), "l"(src));
}

// ---------------------------------------------------------------------------
// Prep: split w = r^2 * proto into fp16 h/m, compute bias.  (proven R5 kernel)
// ---------------------------------------------------------------------------
__global__ void prep_kernel(const float* __restrict__ protos,
                            const float* __restrict__ relevance) {
    int p = blockIdx.x;          // 512
    int d = threadIdx.x;         // 128
    float r  = relevance[d];
    float pv = protos[p * DIM + d];
    float w  = r * r * pv;

    __half h = __float2half_rn(w);
    __half m = __float2half_rn(w - __half2float(h));
    g_w[0][p * DIM + d] = h;
    g_w[1][p * DIM + d] = m;

    float part = w * pv;
    __shared__ float red[4];
    #pragma unroll
    for (int off = 16; off > 0; off >>= 1)
        part += __shfl_down_sync(0xffffffffu, part, off);
    if ((d & 31) == 0) red[d >> 5] = part;
    __syncthreads();
    if (d == 0) g_bias[p] = -0.5f * (red[0] + red[1] + red[2] + red[3]);
}

// ---------------------------------------------------------------------------
// Main: 512 threads, 1 CTA/SM. 3-term fp16 split; hh in f32 acc,
// hM & mH in f16 acc (rate experiment). Warps 4M x 4N, tile 32x8, NCHUNK=32.
// ---------------------------------------------------------------------------
extern __shared__ char smem[];

__global__ void __launch_bounds__(NTHREADS, 1)
grlvq_main(const float* __restrict__ x,
           const float* __restrict__ proto_out,
           float* __restrict__ out) {
    const uint32_t sb = smem_u32(smem);
    const int tid  = threadIdx.x;
    const int wid  = tid >> 5;
    const int lane = tid & 31;
    const int row0 = blockIdx.x * MTILE;
    const int wm = (wid & 3) * 32;      // 4 M-warps
    const int wn = (wid >> 2) * 8;      // 4 N-warps x 8 cols = NCHUNK

    for (int i = tid; i < NPROTO; i += NTHREADS)
        ((float*)(smem + SM_BIAS))[i] = g_bias[i];

    // B chunk: 2 splits x 32 rows x 16 uint4 = 1024 items
    #define ISSUE_B(c, buf)                                                        \
        do {                                                                       \
            for (int i = tid; i < 1024; i += NTHREADS) {                           \
                int mat = i >> 9, rem = i & 511, rr = rem >> 4, q = rem & 15;      \
                const void* src = &g_w[mat][(size_t)((c) * NCHUNK + rr) * DIM + q * 8]; \
                uint32_t dst = sb + SM_B + (buf) * BBUF + mat * MATB               \
                             + rr * ASTRIDE + q * 16;                              \
                cp_async16(dst, src);                                              \
            }                                                                      \
            asm volatile("cp.async.commit_group;" ::: "memory");                   \
        } while (0)

    ISSUE_B(0, 0);
    ISSUE_B(1, 1);

    // ---- A: load x tile, split into fp16 h/m, padded layout ----
    {
        const int r  = tid >> 2;               // 128 rows
        const int cb = (tid & 3) * 32;         // 4 col-blocks
        const float4* xr = (const float4*)(x + (size_t)(row0 + r) * DIM + cb);
        #pragma unroll
        for (int g = 0; g < 4; g++) {
            float4 v0 = xr[g * 2], v1 = xr[g * 2 + 1];
            float xv[8] = {v0.x, v0.y, v0.z, v0.w, v1.x, v1.y, v1.z, v1.w};
            uint32_t hh[4], mm[4];
            #pragma unroll
            for (int q = 0; q < 4; q++) {
                float a0 = xv[2 * q], a1 = xv[2 * q + 1];
                __half h0 = __float2half_rn(a0), h1 = __float2half_rn(a1);
                float r0 = a0 - __half2float(h0), r1f = a1 - __half2float(h1);
                __half m0 = __float2half_rn(r0), m1 = __float2half_rn(r1f);
                hh[q] = ((uint32_t)__half_as_ushort(h1) << 16) | __half_as_ushort(h0);
                mm[q] = ((uint32_t)__half_as_ushort(m1) << 16) | __half_as_ushort(m0);
            }
            uint32_t off = (uint32_t)r * ASTRIDE + (uint32_t)(cb + g * 8) * 2;
            *(uint4*)(smem + SM_A + 0 * ATILE + off) = make_uint4(hh[0], hh[1], hh[2], hh[3]);
            *(uint4*)(smem + SM_A + 1 * ATILE + off) = make_uint4(mm[0], mm[1], mm[2], mm[3]);
        }
    }

    // Running argmax: 4 row slots (mt*2 + half)
    float bestv[4];
    int   besti[4];
    #pragma unroll
    for (int i = 0; i < 4; i++) { bestv[i] = -3.402823466e38f; besti[i] = 0; }

    const uint32_t a_row = (uint32_t)(wm + (lane & 15));
    const uint32_t a_kh  = (uint32_t)(lane >> 4) * 16;
    // ldmatrix.x2: lanes 0..15 supply addresses; rows wn..wn+7, k halves
    const uint32_t b_row = (uint32_t)(wn + (lane & 7));
    const uint32_t b_kh  = (uint32_t)((lane >> 3) & 1) * 16;

    for (int c = 0; c < NCHUNKS; c++) {
        asm volatile("cp.async.wait_group 1;" ::: "memory");
        __syncthreads();
        const uint32_t bbase = sb + SM_B + (c & 1) * BBUF;

        float    accf[2][4];        // hh, f32 acc
        uint32_t acch[2][2];        // hM, f16 acc (f16x2 pairs)
        uint32_t accm[2][2];        // mH, f16 acc
        #pragma unroll
        for (int mt = 0; mt < 2; mt++) {
            #pragma unroll
            for (int j = 0; j < 4; j++) accf[mt][j] = 0.0f;
            acch[mt][0] = acch[mt][1] = 0u;
            accm[mt][0] = accm[mt][1] = 0u;
        }

        #pragma unroll
        for (int kk = 0; kk < 8; kk++) {
            uint32_t ah[2][4], am[2][4];
            #pragma unroll
            for (int mt = 0; mt < 2; mt++) {
                ldsm4(ah[mt], sb + SM_A + 0 * ATILE + (a_row + mt * 16) * ASTRIDE + kk * 32 + a_kh);
                ldsm4(am[mt], sb + SM_A + 1 * ATILE + (a_row + mt * 16) * ASTRIDE + kk * 32 + a_kh);
            }
            uint32_t bH[2], bM[2];
            ldsm2(bH, bbase + 0 * MATB + b_row * ASTRIDE + kk * 32 + b_kh);
            ldsm2(bM, bbase + 1 * MATB + b_row * ASTRIDE + kk * 32 + b_kh);
            #pragma unroll
            for (int mt = 0; mt < 2; mt++) {
                mma_f32(accf[mt], ah[mt], bH);     // hh  (exact path)
                mma_f16(acch[mt], ah[mt], bM);     // hM  (tiny, f16 acc)
                mma_f16(accm[mt], am[mt], bH);     // mH  (tiny, f16 acc)
            }
        }

        // ---- epilogue: fold f16 corrections into f32, bias, argmax ----
        const float* bias_s = (const float*)(smem + SM_BIAS);
        const int cbase = c * NCHUNK + wn + (lane & 3) * 2;
        float b0 = bias_s[cbase], b1 = bias_s[cbase + 1];
        #pragma unroll
        for (int mt = 0; mt < 2; mt++) {
            float2 ch0 = __half22float2(*(__half2*)&acch[mt][0]);
            float2 ch1 = __half22float2(*(__half2*)&acch[mt][1]);
            float2 cm0 = __half22float2(*(__half2*)&accm[mt][0]);
            float2 cm1 = __half22float2(*(__half2*)&accm[mt][1]);
            float v0 = accf[mt][0] + ch0.x + cm0.x + b0;   // row r,   col cbase
            float v1 = accf[mt][1] + ch0.y + cm0.y + b1;   // row r,   col cbase+1
            float v2 = accf[mt][2] + ch1.x + cm1.x + b0;   // row r+8, col cbase
            float v3 = accf[mt][3] + ch1.y + cm1.y + b1;   // row r+8, col cbase+1
            int s0 = mt * 2, s1 = mt * 2 + 1;
            if (v0 > bestv[s0]) { bestv[s0] = v0; besti[s0] = cbase; }
            if (v1 > bestv[s0]) { bestv[s0] = v1; besti[s0] = cbase + 1; }
            if (v2 > bestv[s1]) { bestv[s1] = v2; besti[s1] = cbase; }
            if (v3 > bestv[s1]) { bestv[s1] = v3; besti[s1] = cbase + 1; }
        }

        __syncthreads();
        if (c + 2 < NCHUNKS) ISSUE_B(c + 2, c & 1);
    }

    // ---- cross-thread reduction: 16 candidates per row ----
    float* redv = (float*)(smem + SM_RED);
    int*   redi = (int*)(smem + SM_RED + 8192);
    const int slot = ((wid >> 2) << 2) | (lane & 3);   // 0..15
    #pragma unroll
    for (int sl = 0; sl < 4; sl++) {
        int row = wm + (sl >> 1) * 16 + (sl & 1) * 8 + (lane >> 2);
        redv[row * 16 + slot] = bestv[sl];
        redi[row * 16 + slot] = besti[sl];
    }
    __syncthreads();

    if (tid < MTILE) {
        float bv = redv[tid * 16];
        int   bi = redi[tid * 16];
        #pragma unroll
        for (int j = 1; j < 16; j++) {
            float v  = redv[tid * 16 + j];
            int   ix = redi[tid * 16 + j];
            if (v > bv || (v == bv && ix < bi)) { bv = v; bi = ix; }
        }
        const float4* po = (const float4*)proto_out;
        float4* o = (float4*)(out + (size_t)(row0 + tid) * ODIM);
        o[0] = po[bi * 2];
        o[1] = po[bi * 2 + 1];
    }
}

// ---------------------------------------------------------------------------
extern "C" void kernel_launch(void* const* d_in, const int* in_sizes, int n_in,
                              void* d_out, int out_size) {
    const float* x         = (const float*)d_in[0];  // [65536,128]
    const float* protos    = (const float*)d_in[1];  // [512,128]
    const float* proto_out = (const float*)d_in[2];  // [512,8]
    const float* relevance = (const float*)d_in[3];  // [128]
    float* out = (float*)d_out;                      // [65536,8]

    prep_kernel<<<NPROTO, DIM>>>(protos, relevance);

    cudaFuncSetAttribute(grlvq_main,
                         cudaFuncAttributeMaxDynamicSharedMemorySize, SMEM_TOTAL);
    grlvq_main<<<BATCH / MTILE, NTHREADS, SMEM_TOTAL>>>(x, proto_out, out);
}

// round 12
// speedup vs baseline: 1.4137x; 1.4137x over previous
#include <cuda_runtime.h>
#include <cuda_fp16.h>
#include <cstdint>

#define BATCH   65536
#define DIM     128
#define NPROTO  512
#define ODIM    8
#define MTILE   128
#define NCHUNK  64
#define NCHUNKS 8
#define NTHREADS 512

#define ASTRIDE 272
#define ATILE   (MTILE * ASTRIDE)      // 34816 per split
#define BTILE   (NCHUNK * ASTRIDE)     // 17408 per split
#define BBUF    (2 * BTILE)            // 34816 per buffer (2 splits)

#define SM_BIAS 0
#define SM_A    2048
#define SM_B    (SM_A + 2 * ATILE)     // 71680
#define SM_RED  SM_A
#define SMEM_TOTAL (SM_B + 2 * BBUF)   // 141312 -> 1 CTA/SM

__device__ __align__(16) __half g_w[2][NPROTO * DIM];  // h/m fp16 split of r^2*proto
__device__ float g_bias[NPROTO];

// ---------------- helpers ----------------
__device__ __forceinline__ uint32_t smem_u32(const void* p) {
    uint32_t a;
    asm("{ .reg .u64 t; cvta.to.shared.u64 t, %1; cvt.u32.u64 %0, t; }" : "=r"(a) : "l"(p));
    return a;
}
__device__ __forceinline__ void ldsm4(uint32_t* r, uint32_t a) {
    asm volatile("ldmatrix.sync.aligned.m8n8.x4.shared.b16 {%0,%1,%2,%3}, [%4];"
                 : "=r"(r[0]), "=r"(r[1]), "=r"(r[2]), "=r"(r[3]) : "r"(a));
}
__device__ __forceinline__ void mma16816(float* d, const uint32_t* a, const uint32_t* b) {
    asm volatile(
        "mma.sync.aligned.m16n8k16.row.col.f32.f16.f16.f32 "
        "{%0,%1,%2,%3}, {%4,%5,%6,%7}, {%8,%9}, {%0,%1,%2,%3};"
        : "+f"(d[0]), "+f"(d[1]), "+f"(d[2]), "+f"(d[3])
        : "r"(a[0]), "r"(a[1]), "r"(a[2]), "r"(a[3]), "r"(b[0]), "r"(b[1]));
}
__device__ __forceinline__ void cp_async16(uint32_t dst, const void* src) {
    asm volatile("cp.async.cg.shared.global [%0], [%1], 16;" :: "r"(dst), "l"(src));
}

// ---------------------------------------------------------------------------
// Prep: split w = r^2 * proto into fp16 h/m, compute bias.  (proven)
// ---------------------------------------------------------------------------
__global__ void prep_kernel(const float* __restrict__ protos,
                            const float* __restrict__ relevance) {
    int p = blockIdx.x;          // 512
    int d = threadIdx.x;         // 128
    float r  = relevance[d];
    float pv = protos[p * DIM + d];
    float w  = r * r * pv;

    __half h = __float2half_rn(w);
    __half m = __float2half_rn(w - __half2float(h));
    g_w[0][p * DIM + d] = h;
    g_w[1][p * DIM + d] = m;

    float part = w * pv;
    __shared__ float red[4];
    #pragma unroll
    for (int off = 16; off > 0; off >>= 1)
        part += __shfl_down_sync(0xffffffffu, part, off);
    if ((d & 31) == 0) red[d >> 5] = part;
    __syncthreads();
    if (d == 0) g_bias[p] = -0.5f * (red[0] + red[1] + red[2] + red[3]);
}

// ---------------------------------------------------------------------------
// Main: 512 threads, 1 CTA/SM. A held in registers for the whole kernel.
//   Warps: 8M x 2N; warp tile 16x32; 3 fp16 terms, f32 acc; NCHUNK=64.
// ---------------------------------------------------------------------------
extern __shared__ char smem[];

__global__ void __launch_bounds__(NTHREADS, 1)
grlvq_main(const float* __restrict__ x,
           const float* __restrict__ proto_out,
           float* __restrict__ out) {
    const uint32_t sb = smem_u32(smem);
    const int tid  = threadIdx.x;
    const int wid  = tid >> 5;
    const int lane = tid & 31;
    const int row0 = blockIdx.x * MTILE;
    const int wm = (wid & 7) * 16;      // 8 M-warps x 16 rows
    const int wn = (wid >> 3) * 32;     // 2 N-warps x 32 cols

    for (int i = tid; i < NPROTO; i += NTHREADS)
        ((float*)(smem + SM_BIAS))[i] = g_bias[i];

    // B chunk: 2 splits x 64 rows x 16 uint4 = 2048 items
    #define ISSUE_B(c, buf)                                                        \
        do {                                                                       \
            for (int i = tid; i < 2048; i += NTHREADS) {                           \
                int mat = i >> 10, rem = i & 1023, rr = rem >> 4, q = rem & 15;    \
                const void* src = &g_w[mat][(size_t)((c) * NCHUNK + rr) * DIM + q * 8]; \
                uint32_t dst = sb + SM_B + (buf) * BBUF + mat * BTILE              \
                             + rr * ASTRIDE + q * 16;                              \
                cp_async16(dst, src);                                              \
            }                                                                      \
            asm volatile("cp.async.commit_group;" ::: "memory");                   \
        } while (0)

    ISSUE_B(0, 0);
    ISSUE_B(1, 1);

    // ---- A: load x tile, split into fp16 h/m, padded layout ----
    {
        const int r  = tid >> 2;               // 128 rows
        const int cb = (tid & 3) * 32;
        const float4* xr = (const float4*)(x + (size_t)(row0 + r) * DIM + cb);
        #pragma unroll
        for (int g = 0; g < 4; g++) {
            float4 v0 = xr[g * 2], v1 = xr[g * 2 + 1];
            float xv[8] = {v0.x, v0.y, v0.z, v0.w, v1.x, v1.y, v1.z, v1.w};
            uint32_t hh[4], mm[4];
            #pragma unroll
            for (int q = 0; q < 4; q++) {
                float a0 = xv[2 * q], a1 = xv[2 * q + 1];
                __half h0 = __float2half_rn(a0), h1 = __float2half_rn(a1);
                float r0 = a0 - __half2float(h0), r1f = a1 - __half2float(h1);
                __half m0 = __float2half_rn(r0), m1 = __float2half_rn(r1f);
                hh[q] = ((uint32_t)__half_as_ushort(h1) << 16) | __half_as_ushort(h0);
                mm[q] = ((uint32_t)__half_as_ushort(m1) << 16) | __half_as_ushort(m0);
            }
            uint32_t off = (uint32_t)r * ASTRIDE + (uint32_t)(cb + g * 8) * 2;
            *(uint4*)(smem + SM_A + 0 * ATILE + off) = make_uint4(hh[0], hh[1], hh[2], hh[3]);
            *(uint4*)(smem + SM_A + 1 * ATILE + off) = make_uint4(mm[0], mm[1], mm[2], mm[3]);
        }
    }
    __syncthreads();

    // ---- load A fragments into registers ONCE (16 ldsm4) ----
    uint32_t ah[8][4], am[8][4];
    {
        const uint32_t a_addr = sb + SM_A
            + (uint32_t)(wm + (lane & 15)) * ASTRIDE + (uint32_t)(lane >> 4) * 16;
        #pragma unroll
        for (int kk = 0; kk < 8; kk++) {
            ldsm4(ah[kk], a_addr + kk * 32);
            ldsm4(am[kk], a_addr + ATILE + kk * 32);
        }
    }

    // Running argmax: 2 row slots (rows r, r+8 of warp tile)
    float bestv[2] = {-3.402823466e38f, -3.402823466e38f};
    int   besti[2] = {0, 0};

    const uint32_t b_row = (uint32_t)(wn + ((lane >> 4) & 1) * 8 + (lane & 7));
    const uint32_t b_kh  = (uint32_t)((lane >> 3) & 1) * 16;

    for (int c = 0; c < NCHUNKS; c++) {
        asm volatile("cp.async.wait_group 1;" ::: "memory");
        __syncthreads();
        const uint32_t bbase = sb + SM_B + (c & 1) * BBUF;

        float acc[4][4];                     // 4 n8 slices
        #pragma unroll
        for (int nt = 0; nt < 4; nt++)
            #pragma unroll
            for (int j = 0; j < 4; j++) acc[nt][j] = 0.0f;

        #pragma unroll
        for (int kk = 0; kk < 8; kk++) {
            uint32_t bH[2][4], bM[2][4];
            #pragma unroll
            for (int np = 0; np < 2; np++) {
                uint32_t baddr = bbase + (b_row + np * 16) * ASTRIDE + kk * 32 + b_kh;
                ldsm4(bH[np], baddr);
                ldsm4(bM[np], baddr + BTILE);
            }
            #pragma unroll
            for (int np = 0; np < 2; np++) {
                #pragma unroll
                for (int n2 = 0; n2 < 2; n2++) {
                    float* a4 = acc[np * 2 + n2];
                    mma16816(a4, ah[kk], &bH[np][n2 * 2]);   // h*H
                    mma16816(a4, ah[kk], &bM[np][n2 * 2]);   // h*M
                    mma16816(a4, am[kk], &bH[np][n2 * 2]);   // m*H
                }
            }
        }

        // ---- epilogue: bias + running argmax (ascending cols keep first idx) ----
        const float* bias_s = (const float*)(smem + SM_BIAS);
        const int cb0 = c * NCHUNK + wn + (lane & 3) * 2;
        #pragma unroll
        for (int nt = 0; nt < 4; nt++) {
            const int col = cb0 + nt * 8;
            float b0 = bias_s[col], b1 = bias_s[col + 1];
            float v0 = acc[nt][0] + b0;     // row r
            float v1 = acc[nt][1] + b1;
            float v2 = acc[nt][2] + b0;     // row r+8
            float v3 = acc[nt][3] + b1;
            if (v0 > bestv[0]) { bestv[0] = v0; besti[0] = col; }
            if (v1 > bestv[0]) { bestv[0] = v1; besti[0] = col + 1; }
            if (v2 > bestv[1]) { bestv[1] = v2; besti[1] = col; }
            if (v3 > bestv[1]) { bestv[1] = v3; besti[1] = col + 1; }
        }

        __syncthreads();
        if (c + 2 < NCHUNKS) ISSUE_B(c + 2, c & 1);
    }

    // ---- cross-thread reduction: 8 candidates per row ----
    float* redv = (float*)(smem + SM_RED);
    int*   redi = (int*)(smem + SM_RED + 4096);
    const int slot = ((wid >> 3) << 2) | (lane & 3);   // 0..7
    {
        int r0 = wm + (lane >> 2);
        redv[r0 * 8 + slot] = bestv[0];
        redi[r0 * 8 + slot] = besti[0];
        redv[(r0 + 8) * 8 + slot] = bestv[1];
        redi[(r0 + 8) * 8 + slot] = besti[1];
    }
    __syncthreads();

    if (tid < MTILE) {
        float bv = redv[tid * 8];
        int   bi = redi[tid * 8];
        #pragma unroll
        for (int j = 1; j < 8; j++) {
            float v  = redv[tid * 8 + j];
            int   ix = redi[tid * 8 + j];
            if (v > bv || (v == bv && ix < bi)) { bv = v; bi = ix; }
        }
        const float4* po = (const float4*)proto_out;
        float4* o = (float4*)(out + (size_t)(row0 + tid) * ODIM);
        o[0] = po[bi * 2];
        o[1] = po[bi * 2 + 1];
    }
}

// ---------------------------------------------------------------------------
extern "C" void kernel_launch(void* const* d_in, const int* in_sizes, int n_in,
                              void* d_out, int out_size) {
    const float* x         = (const float*)d_in[0];  // [65536,128]
    const float* protos    = (const float*)d_in[1];  // [512,128]
    const float* proto_out = (const float*)d_in[2];  // [512,8]
    const float* relevance = (const float*)d_in[3];  // [128]
    float* out = (float*)d_out;                      // [65536,8]

    prep_kernel<<<NPROTO, DIM>>>(protos, relevance);

    cudaFuncSetAttribute(grlvq_main,
                         cudaFuncAttributeMaxDynamicSharedMemorySize, SMEM_TOTAL);
    grlvq_main<<<BATCH / MTILE, NTHREADS, SMEM_TOTAL>>>(x, proto_out, out);
}

// round 13
// speedup vs baseline: 1.6245x; 1.1491x over previous
#include <cuda_runtime.h>
#include <cuda_fp16.h>
#include <cstdint>

#define BATCH   65536
#define DIM     128
#define NPROTO  512
#define ODIM    8
#define MTILE   128
#define NCHUNK  64
#define NCHUNKS 8
#define NTHREADS 512

#define BTILE   16384                   // one split chunk: 64 rows x 256B
#define BBUF    (2 * BTILE)             // 32768 per buffer (2 splits)

#define SM_BIAS 0                       // 512 f32
#define SM_A    2048                    // 2 splits x 32768 (128 rows x 256B)
#define SM_B    (SM_A + 65536)          // 67584; 2 bufs
#define SM_MBAR (SM_B + 2 * BBUF)       // 133120; 2 mbarriers
#define SM_RED  SM_A
#define SMEM_TOTAL (SM_MBAR + 32)       // 133152 -> 1 CTA/SM

// g_w stored PRE-SWIZZLED: chunk-contiguous, within chunk r*128 + (d ^ ((r&7)<<3))
__device__ __align__(16) __half g_w[2][NPROTO * DIM];
__device__ float g_bias[NPROTO];

// ---------------- helpers ----------------
__device__ __forceinline__ uint32_t smem_u32(const void* p) {
    uint32_t a;
    asm("{ .reg .u64 t; cvta.to.shared.u64 t, %1; cvt.u32.u64 %0, t; }" : "=r"(a) : "l"(p));
    return a;
}
__device__ __forceinline__ void ldsm4(uint32_t* r, uint32_t a) {
    asm volatile("ldmatrix.sync.aligned.m8n8.x4.shared.b16 {%0,%1,%2,%3}, [%4];"
                 : "=r"(r[0]), "=r"(r[1]), "=r"(r[2]), "=r"(r[3]) : "r"(a));
}
__device__ __forceinline__ void mma16816(float* d, const uint32_t* a, const uint32_t* b) {
    asm volatile(
        "mma.sync.aligned.m16n8k16.row.col.f32.f16.f16.f32 "
        "{%0,%1,%2,%3}, {%4,%5,%6,%7}, {%8,%9}, {%0,%1,%2,%3};"
        : "+f"(d[0]), "+f"(d[1]), "+f"(d[2]), "+f"(d[3])
        : "r"(a[0]), "r"(a[1]), "r"(a[2]), "r"(a[3]), "r"(b[0]), "r"(b[1]));
}
__device__ __forceinline__ void mbar_init(uint32_t a, uint32_t cnt) {
    asm volatile("mbarrier.init.shared.b64 [%0], %1;" :: "r"(a), "r"(cnt) : "memory");
}
__device__ __forceinline__ void mbar_expect_tx(uint32_t a, uint32_t bytes) {
    asm volatile("mbarrier.arrive.expect_tx.shared.b64 _, [%0], %1;"
                 :: "r"(a), "r"(bytes) : "memory");
}
__device__ __forceinline__ void mbar_wait(uint32_t a, uint32_t parity) {
    asm volatile(
        "{\n\t.reg .pred P;\n\t"
        "WL%=:\n\t"
        "mbarrier.try_wait.parity.shared.b64 P, [%0], %1;\n\t"
        "@!P bra WL%=;\n\t}"
        :: "r"(a), "r"(parity) : "memory");
}
__device__ __forceinline__ void bulk_g2s(uint32_t dst, const void* src,
                                         uint32_t bytes, uint32_t mbar) {
    asm volatile(
        "cp.async.bulk.shared::cta.global.mbarrier::complete_tx::bytes [%0], [%1], %2, [%3];"
        :: "r"(dst), "l"(src), "r"(bytes), "r"(mbar) : "memory");
}

// ---------------------------------------------------------------------------
// Prep: fp16 h/m split of w = r^2*proto, stored pre-swizzled chunk-major; bias.
// ---------------------------------------------------------------------------
__global__ void prep_kernel(const float* __restrict__ protos,
                            const float* __restrict__ relevance) {
    int p = blockIdx.x;          // 512
    int d = threadIdx.x;         // 128
    float r  = relevance[d];
    float pv = protos[p * DIM + d];
    float w  = r * r * pv;

    __half h = __float2half_rn(w);
    __half m = __float2half_rn(w - __half2float(h));
    int chunk = p >> 6, rr = p & 63;
    int idx = chunk * (NCHUNK * DIM) + rr * DIM + (d ^ ((rr & 7) << 3));
    g_w[0][idx] = h;
    g_w[1][idx] = m;

    float part = w * pv;
    __shared__ float red[4];
    #pragma unroll
    for (int off = 16; off > 0; off >>= 1)
        part += __shfl_down_sync(0xffffffffu, part, off);
    if ((d & 31) == 0) red[d >> 5] = part;
    __syncthreads();
    if (d == 0) g_bias[p] = -0.5f * (red[0] + red[1] + red[2] + red[3]);
}

// ---------------------------------------------------------------------------
// Main: 512 threads, 1 CTA/SM. A in registers; B via cp.async.bulk + mbarrier.
//   Warps: 8M x 2N; warp tile 16x32; 3 fp16 terms, f32 acc; NCHUNK=64.
// ---------------------------------------------------------------------------
extern __shared__ char smem[];

__global__ void __launch_bounds__(NTHREADS, 1)
grlvq_main(const float* __restrict__ x,
           const float* __restrict__ proto_out,
           float* __restrict__ out) {
    const uint32_t sb = smem_u32(smem);
    const int tid  = threadIdx.x;
    const int wid  = tid >> 5;
    const int lane = tid & 31;
    const int row0 = blockIdx.x * MTILE;
    const int wm = (wid & 7) * 16;      // 8 M-warps x 16 rows
    const int wn = (wid >> 3) * 32;     // 2 N-warps x 32 cols

    // mbarriers
    if (tid == 0) {
        mbar_init(sb + SM_MBAR + 0, 1);
        mbar_init(sb + SM_MBAR + 8, 1);
    }
    __syncthreads();

    // issue B chunks 0,1 (one thread, 2 bulk copies each)
    if (tid == 0) {
        #pragma unroll
        for (int c = 0; c < 2; c++) {
            uint32_t mb = sb + SM_MBAR + c * 8;
            mbar_expect_tx(mb, 2 * BTILE);
            bulk_g2s(sb + SM_B + c * BBUF,
                     (const char*)g_w[0] + (size_t)c * BTILE, BTILE, mb);
            bulk_g2s(sb + SM_B + c * BBUF + BTILE,
                     (const char*)g_w[1] + (size_t)c * BTILE, BTILE, mb);
        }
    }

    for (int i = tid; i < NPROTO; i += NTHREADS)
        ((float*)(smem + SM_BIAS))[i] = g_bias[i];

    // ---- A: load x tile, split into fp16 h/m, swizzled 256B rows ----
    {
        const int r  = tid >> 2;               // 128 rows
        const int cb = (tid & 3) * 32;
        const float4* xr = (const float4*)(x + (size_t)(row0 + r) * DIM + cb);
        #pragma unroll
        for (int g = 0; g < 4; g++) {
            float4 v0 = xr[g * 2], v1 = xr[g * 2 + 1];
            float xv[8] = {v0.x, v0.y, v0.z, v0.w, v1.x, v1.y, v1.z, v1.w};
            uint32_t hh[4], mm[4];
            #pragma unroll
            for (int q = 0; q < 4; q++) {
                float a0 = xv[2 * q], a1 = xv[2 * q + 1];
                __half h0 = __float2half_rn(a0), h1 = __float2half_rn(a1);
                float r0 = a0 - __half2float(h0), r1f = a1 - __half2float(h1);
                __half m0 = __float2half_rn(r0), m1 = __float2half_rn(r1f);
                hh[q] = ((uint32_t)__half_as_ushort(h1) << 16) | __half_as_ushort(h0);
                mm[q] = ((uint32_t)__half_as_ushort(m1) << 16) | __half_as_ushort(m0);
            }
            uint32_t q0  = (uint32_t)(cb + g * 8) * 2;            // byte col
            uint32_t off = (uint32_t)r * 256 + (q0 ^ (((uint32_t)r & 7) << 4));
            *(uint4*)(smem + SM_A +     0 + off) = make_uint4(hh[0], hh[1], hh[2], hh[3]);
            *(uint4*)(smem + SM_A + 32768 + off) = make_uint4(mm[0], mm[1], mm[2], mm[3]);
        }
    }
    __syncthreads();

    // ---- A fragments to registers once (16 ldsm4) ----
    uint32_t ah[8][4], am[8][4];
    {
        const uint32_t arow = (uint32_t)(wm + (lane & 15));
        const uint32_t base = sb + SM_A + arow * 256;
        #pragma unroll
        for (int kk = 0; kk < 8; kk++) {
            uint32_t q0 = (uint32_t)(kk * 32) + ((uint32_t)(lane >> 4)) * 16;
            uint32_t sw = q0 ^ ((arow & 7) << 4);
            ldsm4(ah[kk], base + sw);
            ldsm4(am[kk], base + 32768 + sw);
        }
    }

    float bestv[2] = {-3.402823466e38f, -3.402823466e38f};
    int   besti[2] = {0, 0};

    const uint32_t brow0 = (uint32_t)(wn + ((lane >> 4) & 1) * 8 + (lane & 7));
    const uint32_t b_kh  = ((uint32_t)(lane >> 3) & 1) * 16;

    for (int c = 0; c < NCHUNKS; c++) {
        mbar_wait(sb + SM_MBAR + (c & 1) * 8, (c >> 1) & 1);
        const uint32_t bbase = sb + SM_B + (c & 1) * BBUF;

        float acc[4][4];
        #pragma unroll
        for (int nt = 0; nt < 4; nt++)
            #pragma unroll
            for (int j = 0; j < 4; j++) acc[nt][j] = 0.0f;

        #pragma unroll
        for (int kk = 0; kk < 8; kk++) {
            uint32_t bH[2][4], bM[2][4];
            #pragma unroll
            for (int np = 0; np < 2; np++) {
                uint32_t brow = brow0 + np * 16;
                uint32_t q0   = (uint32_t)(kk * 32) + b_kh;
                uint32_t addr = bbase + brow * 256 + (q0 ^ ((brow & 7) << 4));
                ldsm4(bH[np], addr);
                ldsm4(bM[np], addr + BTILE);
            }
            #pragma unroll
            for (int np = 0; np < 2; np++) {
                #pragma unroll
                for (int n2 = 0; n2 < 2; n2++) {
                    float* a4 = acc[np * 2 + n2];
                    mma16816(a4, ah[kk], &bH[np][n2 * 2]);   // h*H
                    mma16816(a4, ah[kk], &bM[np][n2 * 2]);   // h*M
                    mma16816(a4, am[kk], &bH[np][n2 * 2]);   // m*H
                }
            }
        }

        // ---- epilogue: bias + running argmax (ascending cols keep first idx) ----
        const float* bias_s = (const float*)(smem + SM_BIAS);
        const int cb0 = c * NCHUNK + wn + (lane & 3) * 2;
        #pragma unroll
        for (int nt = 0; nt < 4; nt++) {
            const int col = cb0 + nt * 8;
            float b0 = bias_s[col], b1 = bias_s[col + 1];
            float v0 = acc[nt][0] + b0;     // row r
            float v1 = acc[nt][1] + b1;
            float v2 = acc[nt][2] + b0;     // row r+8
            float v3 = acc[nt][3] + b1;
            if (v0 > bestv[0]) { bestv[0] = v0; besti[0] = col; }
            if (v1 > bestv[0]) { bestv[0] = v1; besti[0] = col + 1; }
            if (v2 > bestv[1]) { bestv[1] = v2; besti[1] = col; }
            if (v3 > bestv[1]) { bestv[1] = v3; besti[1] = col + 1; }
        }

        __syncthreads();                     // all warps done reading slot c&1
        if (c + 2 < NCHUNKS && tid == 0) {
            const int cn = c + 2;
            uint32_t mb = sb + SM_MBAR + (cn & 1) * 8;
            mbar_expect_tx(mb, 2 * BTILE);
            bulk_g2s(sb + SM_B + (cn & 1) * BBUF,
                     (const char*)g_w[0] + (size_t)cn * BTILE, BTILE, mb);
            bulk_g2s(sb + SM_B + (cn & 1) * BBUF + BTILE,
                     (const char*)g_w[1] + (size_t)cn * BTILE, BTILE, mb);
        }
    }

    // ---- cross-thread reduction: 8 candidates per row ----
    float* redv = (float*)(smem + SM_RED);
    int*   redi = (int*)(smem + SM_RED + 4096);
    const int slot = ((wid >> 3) << 2) | (lane & 3);   // 0..7
    {
        int r0 = wm + (lane >> 2);
        redv[r0 * 8 + slot] = bestv[0];
        redi[r0 * 8 + slot] = besti[0];
        redv[(r0 + 8) * 8 + slot] = bestv[1];
        redi[(r0 + 8) * 8 + slot] = besti[1];
    }
    __syncthreads();

    if (tid < MTILE) {
        float bv = redv[tid * 8];
        int   bi = redi[tid * 8];
        #pragma unroll
        for (int j = 1; j < 8; j++) {
            float v  = redv[tid * 8 + j];
            int   ix = redi[tid * 8 + j];
            if (v > bv || (v == bv && ix < bi)) { bv = v; bi = ix; }
        }
        const float4* po = (const float4*)proto_out;
        float4* o = (float4*)(out + (size_t)(row0 + tid) * ODIM);
        o[0] = po[bi * 2];
        o[1] = po[bi * 2 + 1];
    }
}

// ---------------------------------------------------------------------------
extern "C" void kernel_launch(void* const* d_in, const int* in_sizes, int n_in,
                              void* d_out, int out_size) {
    const float* x         = (const float*)d_in[0];  // [65536,128]
    const float* protos    = (const float*)d_in[1];  // [512,128]
    const float* proto_out = (const float*)d_in[2];  // [512,8]
    const float* relevance = (const float*)d_in[3];  // [128]
    float* out = (float*)d_out;                      // [65536,8]

    prep_kernel<<<NPROTO, DIM>>>(protos, relevance);

    cudaFuncSetAttribute(grlvq_main,
                         cudaFuncAttributeMaxDynamicSharedMemorySize, SMEM_TOTAL);
    grlvq_main<<<BATCH / MTILE, NTHREADS, SMEM_TOTAL>>>(x, proto_out, out);
}